// round 11
// baseline (speedup 1.0000x reference)
#include <cuda_runtime.h>
#include <cuda_fp16.h>
#include <cstdint>

#define BB 128
#define TQ 64
#define TK 200
#define TKP 224
#define DD 64
#define HH 10
#define NTHREADS 448           // 14 warps; 2 CTAs per batch, 2 CTAs per SM

#define ASTRIDE 144            // A / SEQK row stride bytes (72 fp16)
#define PSTRIDE 432            // P row stride bytes (216 fp16)
#define AHSTRIDE 4608          // A tile per-h stride (32t x 144B)

// ---- smem byte offsets (per half-CTA: 32 t-rows) ----
#define SEQK_B   0             // fp16 seq k-major [224][144B]         32,256
#define ABUF_B   32256         // fp16 A[10][32t][144B]                46,080
#define P_B      78336         // fp16 P [32t][432B]                   13,824
#define TGT_B    92160         // float [32][65]                        8,320
#define AW_B     100480        // float [10][64] (x256)                 2,560
#define DEC_B    103040        // float [224]                             896
#define VAL_B    103936        // float [224]                             896
#define AB_B     104832        // float [16]
#define AO_B     104896        // float [16]
#define FR_B     104960        // float [64]
#define FI_B     105216        // float [64]
#define PART_B   105472        // float [32][8] row partial sums        1,024
#define SMEM_TOTAL_B 106496

static __device__ __forceinline__ uint32_t smem_u32(const void* p) {
    uint32_t a;
    asm("{ .reg .u64 t; cvta.to.shared.u64 t, %1; cvt.u32.u64 %0, t; }" : "=r"(a) : "l"(p));
    return a;
}
static __device__ __forceinline__ void ldsm_x4(uint32_t* r, uint32_t addr) {
    asm volatile("ldmatrix.sync.aligned.m8n8.x4.shared.b16 {%0,%1,%2,%3}, [%4];"
                 : "=r"(r[0]), "=r"(r[1]), "=r"(r[2]), "=r"(r[3]) : "r"(addr));
}
static __device__ __forceinline__ void ldsm_x4t(uint32_t* r, uint32_t addr) {
    asm volatile("ldmatrix.sync.aligned.m8n8.x4.trans.shared.b16 {%0,%1,%2,%3}, [%4];"
                 : "=r"(r[0]), "=r"(r[1]), "=r"(r[2]), "=r"(r[3]) : "r"(addr));
}
static __device__ __forceinline__ void ldsm_x2(uint32_t* r, uint32_t addr) {
    asm volatile("ldmatrix.sync.aligned.m8n8.x2.shared.b16 {%0,%1}, [%2];"
                 : "=r"(r[0]), "=r"(r[1]) : "r"(addr));
}
static __device__ __forceinline__ void ldsm_x2t(uint32_t* r, uint32_t addr) {
    asm volatile("ldmatrix.sync.aligned.m8n8.x2.trans.shared.b16 {%0,%1}, [%2];"
                 : "=r"(r[0]), "=r"(r[1]) : "r"(addr));
}
static __device__ __forceinline__ void mma_f16(float* c, const uint32_t* a, uint32_t b0, uint32_t b1) {
    asm volatile("mma.sync.aligned.m16n8k16.row.col.f32.f16.f16.f32 "
                 "{%0,%1,%2,%3}, {%4,%5,%6,%7}, {%8,%9}, {%0,%1,%2,%3};"
                 : "+f"(c[0]), "+f"(c[1]), "+f"(c[2]), "+f"(c[3])
                 : "r"(a[0]), "r"(a[1]), "r"(a[2]), "r"(a[3]), "r"(b0), "r"(b1));
}
static __device__ __forceinline__ float htanh(float x) {
    float y; asm("tanh.approx.f32 %0, %1;" : "=f"(y) : "f"(x)); return y;
}

__global__ __launch_bounds__(NTHREADS, 2)
void fta_kernel(const float* __restrict__ seq,
                const float* __restrict__ dtn,
                const float* __restrict__ target,
                const int*   __restrict__ vmask,
                const float* __restrict__ fr,
                const float* __restrict__ fi,
                const float* __restrict__ Aw,
                const float* __restrict__ Ab,
                const float* __restrict__ Aout,
                float* __restrict__ out)
{
    extern __shared__ char smc[];
    const uint32_t sbase = smem_u32(smc);
    float* sTgt  = (float*)(smc + TGT_B);
    float* sAw   = (float*)(smc + AW_B);
    float* sDec  = (float*)(smc + DEC_B);
    float* sVal  = (float*)(smc + VAL_B);
    float* sAb   = (float*)(smc + AB_B);
    float* sAo   = (float*)(smc + AO_B);
    float* sFr   = (float*)(smc + FR_B);
    float* sFi   = (float*)(smc + FI_B);
    float* sPart = (float*)(smc + PART_B);

    const int b    = blockIdx.x >> 1;          // batch
    const int half = blockIdx.x & 1;           // t-half: rows [half*32, half*32+32)
    const int tid  = threadIdx.x;
    const int lane = tid & 31;
    const int warp = tid >> 5;                 // 0..13

    // ---------------- Phase A: gmem -> smem ----------------
    {
        const float4* g4 = (const float4*)(seq + (size_t)b * TK * DD);
        #pragma unroll
        for (int n = 0; n < TKP * 16 / NTHREADS; n++) {    // 8 iters
            int i = tid + n * NTHREADS;
            int k = i >> 4, d4 = i & 15;
            float4 v = make_float4(0.f, 0.f, 0.f, 0.f);
            if (k < TK) v = g4[k * 16 + d4];
            *(__half2*)(smc + SEQK_B + k * ASTRIDE + d4 * 8)     = __floats2half2_rn(v.x, v.y);
            *(__half2*)(smc + SEQK_B + k * ASTRIDE + d4 * 8 + 4) = __floats2half2_rn(v.z, v.w);
        }
        const float* gT = target + (size_t)b * TQ * DD + half * 32 * DD;
        for (int i = tid; i < 32 * DD; i += NTHREADS) {
            int t = i >> 6, d = i & 63;
            sTgt[t * 65 + d] = gT[i];
        }
        for (int i = tid; i < HH * DD; i += NTHREADS) sAw[i] = Aw[i] * 256.0f;
        if (tid < DD) { sFr[tid] = fr[tid]; sFi[tid] = fi[tid]; }
        if (tid < 16) {
            sAb[tid] = (tid < HH) ? Ab[tid]   : 0.f;
            sAo[tid] = (tid < HH) ? Aout[tid] : 0.f;
        }
        if (tid < 256) {
            sPart[tid] = 0.f;                              // zero partials (incl. pad col 7)
            // zero P columns 200-215 (bytes 400..431) for phase E's 13th k-chunk
            int row = tid >> 3, off = 400 + (tid & 7) * 4;
            *(uint32_t*)(smc + P_B + row * PSTRIDE + off) = 0u;
        }
    }
    __syncthreads();

    // ---------------- Phase B: Fourier decay (R9-proven) + build 10 A tiles ----------------
    if (tid < TKP) {
        float dec = 0.f, val = 0.f;
        if (tid < TK) {
            const int   m  = vmask[b * TK + tid];
            const float dt = dtn[b * TK + tid];
            const float th = (3.14159265358979323846f / 63.f) * dt;
            float acc = 0.f;
            #pragma unroll 8
            for (int j = 0; j < DD; j++) {
                float s, c;
                __sincosf(th * (float)j, &s, &c);
                acc = fmaf(c, sFr[j], acc);
                acc = fmaf(-s, sFi[j], acc);
            }
            float dcy = fminf(fmaxf(acc * (1.f / 128.f), 0.f), 1.f);
            if (m != 0) { dec = dcy; val = 1.f; }
        }
        sDec[tid] = dec;
        sVal[tid] = val;
    }
    for (int i = tid; i < HH * 1024; i += NTHREADS) {      // 10h x 32t x 32 half2-pairs
        int h = i >> 10, rem = i & 1023;
        int t = rem >> 5, dp = (rem & 31) << 1;
        float a0 = sTgt[t * 65 + dp]     * sAw[h * 64 + dp];
        float a1 = sTgt[t * 65 + dp + 1] * sAw[h * 64 + dp + 1];
        *(__half2*)(smc + ABUF_B + h * AHSTRIDE + t * ASTRIDE + dp * 2) = __floats2half2_rn(a0, a1);
    }
    __syncthreads();

    // ---------------- Phase C: TN score GEMM, 14 warps (2t x 7n), h-pairs share B ----------------
    const int tg  = warp / 7;                  // 0..1
    const int ng  = warp % 7;                  // 0..6
    const int t0  = tg * 16;
    const bool wide = (ng < 4);
    const int n0  = wide ? ng * 32 : 128 + (ng - 4) * 24;  // 4x32 + 3x24 = 200 cols exactly
    const int g   = lane >> 2;
    const int q2  = (lane & 3) * 2;

    float sc[16];
    {
        const uint32_t rowSel = (uint32_t)((lane & 7) + ((lane >> 3) & 1) * 8);
        const uint32_t aBase  = sbase + ABUF_B + (uint32_t)((t0 + rowSel) * ASTRIDE)
                              + (uint32_t)((lane >> 4) * 16);
        const uint32_t bRow   = (uint32_t)(n0 + (lane & 7) + ((lane >> 4) << 3));
        const uint32_t bBase  = sbase + SEQK_B + bRow * ASTRIDE + (uint32_t)(((lane >> 3) & 1) * 16);
        const uint32_t b2Base = sbase + SEQK_B + (uint32_t)((n0 + 16 + (lane & 7)) * ASTRIDE)
                              + (uint32_t)(((lane >> 3) & 1) * 16);

        #pragma unroll
        for (int i = 0; i < 16; i++) sc[i] = 0.f;

        for (int h = 0; h < HH; h += 2) {
            float acc0[16], acc1[16];
            #pragma unroll
            for (int i = 0; i < 16; i++) { acc0[i] = 0.f; acc1[i] = 0.f; }

            const uint32_t aA0 = aBase + (uint32_t)(h * AHSTRIDE);
            const uint32_t aA1 = aA0 + AHSTRIDE;
            #pragma unroll
            for (int ks = 0; ks < 4; ks++) {
                const uint32_t d0b = (uint32_t)(ks * 32);
                uint32_t bb[8];
                ldsm_x4(bb, bBase + d0b);                       // tokens n0..n0+15
                if (wide) ldsm_x4(bb + 4, bBase + 2304 + d0b);  // tokens n0+16..n0+31
                else      ldsm_x2(bb + 4, b2Base + d0b);        // tokens n0+16..n0+23
                uint32_t af0[4], af1[4];
                ldsm_x4(af0, aA0 + d0b);
                ldsm_x4(af1, aA1 + d0b);
                mma_f16(acc0 + 0, af0, bb[0], bb[1]);
                mma_f16(acc0 + 4, af0, bb[2], bb[3]);
                mma_f16(acc0 + 8, af0, bb[4], bb[5]);
                mma_f16(acc1 + 0, af1, bb[0], bb[1]);
                mma_f16(acc1 + 4, af1, bb[2], bb[3]);
                mma_f16(acc1 + 8, af1, bb[4], bb[5]);
                if (wide) {
                    mma_f16(acc0 + 12, af0, bb[6], bb[7]);
                    mma_f16(acc1 + 12, af1, bb[6], bb[7]);
                }
            }

            const float ao0 = sAo[h],     ab0 = sAb[h];
            const float ao1 = sAo[h + 1], ab1 = sAb[h + 1];
            const int nel = wide ? 16 : 12;
            #pragma unroll
            for (int i = 0; i < 16; i++) {
                if (i < nel) {
                    float x0 = fmaf(acc0[i], 0.00390625f, ab0);
                    float x1 = fmaf(acc1[i], 0.00390625f, ab1);
                    sc[i] = fmaf(ao0, htanh(x0), sc[i]);
                    sc[i] = fmaf(ao1, htanh(x1), sc[i]);
                }
            }
        }
    }

    // ---------------- Phase D: softmax + decay from registers -> fp16 P ----------------
    {
        const int nOct = wide ? 4 : 3;
        float ev[16];
        float se = 0.f, so = 0.f;
        #pragma unroll
        for (int o = 0; o < 4; o++) {
            if (o < nOct) {
                int c = n0 + 8 * o + q2;
                float2 v = *(float2*)&sVal[c];
                float e0 = v.x * __expf(sc[4 * o + 0]);
                float e1 = v.y * __expf(sc[4 * o + 1]);
                float e2 = v.x * __expf(sc[4 * o + 2]);
                float e3 = v.y * __expf(sc[4 * o + 3]);
                ev[4 * o + 0] = e0; ev[4 * o + 1] = e1;
                ev[4 * o + 2] = e2; ev[4 * o + 3] = e3;
                se += e0 + e1;
                so += e2 + e3;
            }
        }
        se += __shfl_xor_sync(0xffffffffu, se, 1);
        se += __shfl_xor_sync(0xffffffffu, se, 2);
        so += __shfl_xor_sync(0xffffffffu, so, 1);
        so += __shfl_xor_sync(0xffffffffu, so, 2);
        if ((lane & 3) == 0) {
            sPart[(t0 + g) * 8 + ng]     = se;
            sPart[(t0 + g + 8) * 8 + ng] = so;
        }
        __syncthreads();   // phase C smem reads done + partials visible

        float4 pe0 = ((float4*)&sPart[(t0 + g) * 8])[0];
        float4 pe1 = ((float4*)&sPart[(t0 + g) * 8])[1];
        float4 po0 = ((float4*)&sPart[(t0 + g + 8) * 8])[0];
        float4 po1 = ((float4*)&sPart[(t0 + g + 8) * 8])[1];
        const float invE = __fdividef(1.f, pe0.x + pe0.y + pe0.z + pe0.w + pe1.x + pe1.y + pe1.z + pe1.w);
        const float invO = __fdividef(1.f, po0.x + po0.y + po0.z + po0.w + po1.x + po1.y + po1.z + po1.w);

        char* rowE = smc + P_B + (t0 + g) * PSTRIDE;
        char* rowO = smc + P_B + (t0 + g + 8) * PSTRIDE;
        #pragma unroll
        for (int o = 0; o < 4; o++) {
            if (o < nOct) {
                int c = n0 + 8 * o + q2;
                float2 d = *(float2*)&sDec[c];
                *(__half2*)(rowE + c * 2) =
                    __floats2half2_rn(ev[4 * o + 0] * invE * d.x, ev[4 * o + 1] * invE * d.y);
                *(__half2*)(rowO + c * 2) =
                    __floats2half2_rn(ev[4 * o + 2] * invO * d.x, ev[4 * o + 3] * invO * d.y);
            }
        }
    }
    __syncthreads();

    // ---------------- Phase E: context = P @ seq via MMA (14 tiles: 2t x 7dg) ----------------
    {
        const uint32_t rowSel = (uint32_t)((lane & 7) + ((lane >> 3) & 1) * 8);
        const int rr = lane >> 2, cc = (lane & 3) * 2;
        float* gout = out + (size_t)b * TQ * DD + half * 32 * DD;

        const int tg2 = warp / 7;          // 0..1
        const int dg  = warp % 7;          // 0..6
        const int t0e = tg2 * 16;
        const uint32_t pBase = sbase + P_B + (uint32_t)((t0e + rowSel) * PSTRIDE)
                             + (uint32_t)((lane >> 4) * 16);
        if (dg < 6) {
            const int d0 = dg * 8;         // 8-wide tile
            const uint32_t kBase = sbase + SEQK_B + rowSel * ASTRIDE + (uint32_t)(d0 * 2);
            float accA[4] = {0.f, 0.f, 0.f, 0.f};
            #pragma unroll
            for (int kc = 0; kc < 13; kc++) {
                uint32_t a[4], bb2[2];
                ldsm_x4(a, pBase + (uint32_t)(kc * 32));
                ldsm_x2t(bb2, kBase + (uint32_t)(kc * 16) * ASTRIDE);
                mma_f16(accA, a, bb2[0], bb2[1]);
            }
            *(float2*)(gout + (t0e + rr) * 64 + d0 + cc)     = make_float2(accA[0], accA[1]);
            *(float2*)(gout + (t0e + rr + 8) * 64 + d0 + cc) = make_float2(accA[2], accA[3]);
        } else {
            const int d0 = 48;             // 16-wide tile (cols 48..63)
            const uint32_t kBase = sbase + SEQK_B + rowSel * ASTRIDE
                                 + (uint32_t)((d0 + ((lane >> 4) * 8)) * 2);
            float accA[4] = {0.f, 0.f, 0.f, 0.f};
            float accB[4] = {0.f, 0.f, 0.f, 0.f};
            #pragma unroll
            for (int kc = 0; kc < 13; kc++) {
                uint32_t a[4], bb[4];
                ldsm_x4(a, pBase + (uint32_t)(kc * 32));
                ldsm_x4t(bb, kBase + (uint32_t)(kc * 16) * ASTRIDE);
                mma_f16(accA, a, bb[0], bb[1]);
                mma_f16(accB, a, bb[2], bb[3]);
            }
            *(float2*)(gout + (t0e + rr) * 64 + d0 + cc)         = make_float2(accA[0], accA[1]);
            *(float2*)(gout + (t0e + rr + 8) * 64 + d0 + cc)     = make_float2(accA[2], accA[3]);
            *(float2*)(gout + (t0e + rr) * 64 + d0 + 8 + cc)     = make_float2(accB[0], accB[1]);
            *(float2*)(gout + (t0e + rr + 8) * 64 + d0 + 8 + cc) = make_float2(accB[2], accB[3]);
        }
    }
}

extern "C" void kernel_launch(void* const* d_in, const int* in_sizes, int n_in,
                              void* d_out, int out_size)
{
    const float* seq    = (const float*)d_in[0];
    const float* dtn    = (const float*)d_in[1];
    const float* target = (const float*)d_in[2];
    const int*   vmask  = (const int*)  d_in[3];
    const float* fr     = (const float*)d_in[4];
    const float* fi     = (const float*)d_in[5];
    const float* Aw     = (const float*)d_in[6];
    const float* Ab     = (const float*)d_in[7];
    const float* Aout   = (const float*)d_in[8];
    float* out = (float*)d_out;

    cudaFuncSetAttribute(fta_kernel, cudaFuncAttributeMaxDynamicSharedMemorySize, SMEM_TOTAL_B);
    fta_kernel<<<BB * 2, NTHREADS, SMEM_TOTAL_B>>>(seq, dtn, target, vmask, fr, fi, Aw, Ab, Aout, out);
}

// round 12
// speedup vs baseline: 1.0269x; 1.0269x over previous
#include <cuda_runtime.h>
#include <cuda_fp16.h>
#include <cstdint>

#define BB 128
#define TQ 64
#define TK 200
#define TKP 224
#define DD 64
#define HH 10
#define NTHREADS 896

#define ASTRIDE 144            // A / SEQK row stride bytes (72 fp16)
#define PSTRIDE 432            // P row stride bytes (216 fp16)

// ---- smem byte offsets ----
#define SEQK_B   0             // fp16 seq k-major [224][144B]         32,256
#define ABUF_B   32256         // fp16 A[10][64t][144B]                92,160
#define P_B      124416        // fp16 P [64t][432B]                   27,648
#define TGT_B    152064        // float [64][65]                       16,640
#define AW_B     168704        // float [10][64]                        2,560
#define DEC_B    171264        // float [224]                             896
#define VAL_B    172160        // float [224]                             896
#define AB_B     173056        // float [16]
#define AO_B     173120        // float [16]
#define FR_B     173184        // float [64]
#define FI_B     173440        // float [64]
#define PART_B   173696        // float [64][8] row partial sums        2,048
#define SMEM_TOTAL_B 175744

static __device__ __forceinline__ uint32_t smem_u32(const void* p) {
    uint32_t a;
    asm("{ .reg .u64 t; cvta.to.shared.u64 t, %1; cvt.u32.u64 %0, t; }" : "=r"(a) : "l"(p));
    return a;
}
static __device__ __forceinline__ void ldsm_x4(uint32_t* r, uint32_t addr) {
    asm volatile("ldmatrix.sync.aligned.m8n8.x4.shared.b16 {%0,%1,%2,%3}, [%4];"
                 : "=r"(r[0]), "=r"(r[1]), "=r"(r[2]), "=r"(r[3]) : "r"(addr));
}
static __device__ __forceinline__ void ldsm_x4t(uint32_t* r, uint32_t addr) {
    asm volatile("ldmatrix.sync.aligned.m8n8.x4.trans.shared.b16 {%0,%1,%2,%3}, [%4];"
                 : "=r"(r[0]), "=r"(r[1]), "=r"(r[2]), "=r"(r[3]) : "r"(addr));
}
static __device__ __forceinline__ void ldsm_x2(uint32_t* r, uint32_t addr) {
    asm volatile("ldmatrix.sync.aligned.m8n8.x2.shared.b16 {%0,%1}, [%2];"
                 : "=r"(r[0]), "=r"(r[1]) : "r"(addr));
}
static __device__ __forceinline__ void ldsm_x2t(uint32_t* r, uint32_t addr) {
    asm volatile("ldmatrix.sync.aligned.m8n8.x2.trans.shared.b16 {%0,%1}, [%2];"
                 : "=r"(r[0]), "=r"(r[1]) : "r"(addr));
}
static __device__ __forceinline__ void mma_f16(float* c, const uint32_t* a, uint32_t b0, uint32_t b1) {
    asm volatile("mma.sync.aligned.m16n8k16.row.col.f32.f16.f16.f32 "
                 "{%0,%1,%2,%3}, {%4,%5,%6,%7}, {%8,%9}, {%0,%1,%2,%3};"
                 : "+f"(c[0]), "+f"(c[1]), "+f"(c[2]), "+f"(c[3])
                 : "r"(a[0]), "r"(a[1]), "r"(a[2]), "r"(a[3]), "r"(b0), "r"(b1));
}
static __device__ __forceinline__ float htanh(float x) {
    float y; asm("tanh.approx.f32 %0, %1;" : "=f"(y) : "f"(x)); return y;
}

__global__ __launch_bounds__(NTHREADS, 1)
void fta_kernel(const float* __restrict__ seq,
                const float* __restrict__ dtn,
                const float* __restrict__ target,
                const int*   __restrict__ vmask,
                const float* __restrict__ fr,
                const float* __restrict__ fi,
                const float* __restrict__ Aw,
                const float* __restrict__ Ab,
                const float* __restrict__ Aout,
                float* __restrict__ out)
{
    extern __shared__ char smc[];
    const uint32_t sbase = smem_u32(smc);
    float* sTgt  = (float*)(smc + TGT_B);
    float* sAw   = (float*)(smc + AW_B);
    float* sDec  = (float*)(smc + DEC_B);
    float* sVal  = (float*)(smc + VAL_B);
    float* sAb   = (float*)(smc + AB_B);
    float* sAo   = (float*)(smc + AO_B);
    float* sFr   = (float*)(smc + FR_B);
    float* sFi   = (float*)(smc + FI_B);
    float* sPart = (float*)(smc + PART_B);

    const int b    = blockIdx.x;
    const int tid  = threadIdx.x;
    const int lane = tid & 31;
    const int warp = tid >> 5;

    // ---------------- Phase A: gmem -> smem (SEQK only; no transpose) ----------------
    {
        const float4* g4 = (const float4*)(seq + (size_t)b * TK * DD);
        #pragma unroll
        for (int n = 0; n < TKP * 16 / NTHREADS; n++) {    // 4 iters
            int i = tid + n * NTHREADS;
            int k = i >> 4, d4 = i & 15;
            float4 v = make_float4(0.f, 0.f, 0.f, 0.f);
            if (k < TK) v = g4[k * 16 + d4];
            *(__half2*)(smc + SEQK_B + k * ASTRIDE + d4 * 8)     = __floats2half2_rn(v.x, v.y);
            *(__half2*)(smc + SEQK_B + k * ASTRIDE + d4 * 8 + 4) = __floats2half2_rn(v.z, v.w);
        }
        const float* gT = target + (size_t)b * TQ * DD;
        for (int i = tid; i < TQ * DD; i += NTHREADS) {
            int t = i >> 6, d = i & 63;
            sTgt[t * 65 + d] = gT[i];
        }
        if (tid < HH * DD) sAw[tid] = Aw[tid];
        if (tid < DD) { sFr[tid] = fr[tid]; sFi[tid] = fi[tid]; }
        if (tid < 16) {
            sAb[tid] = (tid < HH) ? Ab[tid]   : 0.f;
            sAo[tid] = (tid < HH) ? Aout[tid] : 0.f;
        }
        if (tid < 512) {
            sPart[tid] = 0.f;                              // zero partials (incl. pad col 7)
            // zero P columns 200-215 (bytes 400..431) for phase E's 13th k-chunk
            int row = tid >> 3, off = 400 + (tid & 7) * 4;
            *(uint32_t*)(smc + P_B + row * PSTRIDE + off) = 0u;
        }
    }
    __syncthreads();

    // ---------------- Phase B: Fourier decay + build ALL 10 A tiles ----------------
    if (tid < TKP) {
        float dec = 0.f, val = 0.f;
        if (tid < TK) {
            const int   m  = vmask[b * TK + tid];
            const float dt = dtn[b * TK + tid];
            const float th = (3.14159265358979323846f / 63.f) * dt;
            float acc = 0.f;
            #pragma unroll 8
            for (int j = 0; j < DD; j++) {
                float s, c;
                __sincosf(th * (float)j, &s, &c);
                acc = fmaf(c, sFr[j], acc);
                acc = fmaf(-s, sFi[j], acc);
            }
            float dcy = fminf(fmaxf(acc * (1.f / 128.f), 0.f), 1.f);
            if (m != 0) { dec = dcy; val = 1.f; }
        }
        sDec[tid] = dec;
        sVal[tid] = val;
    }
    for (int i = tid; i < HH * 2048; i += NTHREADS) {
        int h = i >> 11, rem = i & 2047;
        int t = rem >> 5, dp = (rem & 31) << 1;
        float a0 = sTgt[t * 65 + dp]     * sAw[h * 64 + dp];
        float a1 = sTgt[t * 65 + dp + 1] * sAw[h * 64 + dp + 1];
        *(__half2*)(smc + ABUF_B + h * 9216 + t * ASTRIDE + dp * 2) = __floats2half2_rn(a0, a1);
    }
    __syncthreads();

    // ---------------- Phase C: TN score GEMM, 28 warps; B(ks0,1) persistent in regs ----------------
    const int tg  = warp / 7;                  // 0..3
    const int ng  = warp % 7;                  // 0..6
    const int t0  = tg * 16;
    const bool wide = (ng < 4);
    const int n0  = wide ? ng * 32 : 128 + (ng - 4) * 24;  // 4x32 + 3x24 = 200 cols exactly
    const int g   = lane >> 2;
    const int q2  = (lane & 3) * 2;

    float sc[16];
    {
        const uint32_t rowSel = (uint32_t)((lane & 7) + ((lane >> 3) & 1) * 8);
        const uint32_t aBase  = sbase + ABUF_B + (uint32_t)((t0 + rowSel) * ASTRIDE)
                              + (uint32_t)((lane >> 4) * 16);
        const uint32_t bRow   = (uint32_t)(n0 + (lane & 7) + ((lane >> 4) << 3));
        const uint32_t bBase  = sbase + SEQK_B + bRow * ASTRIDE + (uint32_t)(((lane >> 3) & 1) * 16);
        const uint32_t b2Base = sbase + SEQK_B + (uint32_t)((n0 + 16 + (lane & 7)) * ASTRIDE)
                              + (uint32_t)(((lane >> 3) & 1) * 16);

        #pragma unroll
        for (int i = 0; i < 16; i++) sc[i] = 0.f;

        // persistent B fragments for ks=0,1 (h-invariant)
        uint32_t bk0[8], bk1[8];
        ldsm_x4(bk0, bBase + 0);
        if (wide) ldsm_x4(bk0 + 4, bBase + 2304 + 0);
        else      ldsm_x2(bk0 + 4, b2Base + 0);
        ldsm_x4(bk1, bBase + 32);
        if (wide) ldsm_x4(bk1 + 4, bBase + 2304 + 32);
        else      ldsm_x2(bk1 + 4, b2Base + 32);

        for (int h = 0; h < HH; h++) {
            const float abv = sAb[h], ao = sAo[h];
            float acc[16];
            #pragma unroll
            for (int i = 0; i < 16; i++) acc[i] = abv;     // bias folded into accumulator

            const uint32_t aAddr = aBase + (uint32_t)(h * 9216);
            uint32_t af[4];

            // ks = 0 (B held)
            ldsm_x4(af, aAddr + 0);
            mma_f16(acc + 0, af, bk0[0], bk0[1]);
            mma_f16(acc + 4, af, bk0[2], bk0[3]);
            mma_f16(acc + 8, af, bk0[4], bk0[5]);
            if (wide) mma_f16(acc + 12, af, bk0[6], bk0[7]);
            // ks = 1 (B held)
            ldsm_x4(af, aAddr + 32);
            mma_f16(acc + 0, af, bk1[0], bk1[1]);
            mma_f16(acc + 4, af, bk1[2], bk1[3]);
            mma_f16(acc + 8, af, bk1[4], bk1[5]);
            if (wide) mma_f16(acc + 12, af, bk1[6], bk1[7]);
            // ks = 2 (B transient)
            {
                uint32_t bb[8];
                ldsm_x4(bb, bBase + 64);
                if (wide) ldsm_x4(bb + 4, bBase + 2304 + 64);
                else      ldsm_x2(bb + 4, b2Base + 64);
                ldsm_x4(af, aAddr + 64);
                mma_f16(acc + 0, af, bb[0], bb[1]);
                mma_f16(acc + 4, af, bb[2], bb[3]);
                mma_f16(acc + 8, af, bb[4], bb[5]);
                if (wide) mma_f16(acc + 12, af, bb[6], bb[7]);
            }
            // ks = 3 (B transient)
            {
                uint32_t bb[8];
                ldsm_x4(bb, bBase + 96);
                if (wide) ldsm_x4(bb + 4, bBase + 2304 + 96);
                else      ldsm_x2(bb + 4, b2Base + 96);
                ldsm_x4(af, aAddr + 96);
                mma_f16(acc + 0, af, bb[0], bb[1]);
                mma_f16(acc + 4, af, bb[2], bb[3]);
                mma_f16(acc + 8, af, bb[4], bb[5]);
                if (wide) mma_f16(acc + 12, af, bb[6], bb[7]);
            }

            // epilogue: sc += ao * tanh(acc)   (bias already inside acc)
            const int nel = wide ? 16 : 12;
            #pragma unroll
            for (int i = 0; i < 16; i++) {
                if (i < nel) sc[i] = fmaf(ao, htanh(acc[i]), sc[i]);
            }
        }
    }

    // ---------------- Phase D: softmax + decay from registers -> fp16 P ----------------
    {
        const int nOct = wide ? 4 : 3;
        float ev[16];
        float se = 0.f, so = 0.f;
        #pragma unroll
        for (int o = 0; o < 4; o++) {
            if (o < nOct) {
                int c = n0 + 8 * o + q2;
                float2 v = *(float2*)&sVal[c];
                float e0 = v.x * __expf(sc[4 * o + 0]);
                float e1 = v.y * __expf(sc[4 * o + 1]);
                float e2 = v.x * __expf(sc[4 * o + 2]);
                float e3 = v.y * __expf(sc[4 * o + 3]);
                ev[4 * o + 0] = e0; ev[4 * o + 1] = e1;
                ev[4 * o + 2] = e2; ev[4 * o + 3] = e3;
                se += e0 + e1;
                so += e2 + e3;
            }
        }
        se += __shfl_xor_sync(0xffffffffu, se, 1);
        se += __shfl_xor_sync(0xffffffffu, se, 2);
        so += __shfl_xor_sync(0xffffffffu, so, 1);
        so += __shfl_xor_sync(0xffffffffu, so, 2);
        if ((lane & 3) == 0) {
            sPart[(t0 + g) * 8 + ng]     = se;
            sPart[(t0 + g + 8) * 8 + ng] = so;
        }
        __syncthreads();   // phase C smem reads done + partials visible

        float4 pe0 = ((float4*)&sPart[(t0 + g) * 8])[0];
        float4 pe1 = ((float4*)&sPart[(t0 + g) * 8])[1];
        float4 po0 = ((float4*)&sPart[(t0 + g + 8) * 8])[0];
        float4 po1 = ((float4*)&sPart[(t0 + g + 8) * 8])[1];
        const float invE = __fdividef(1.f, pe0.x + pe0.y + pe0.z + pe0.w + pe1.x + pe1.y + pe1.z + pe1.w);
        const float invO = __fdividef(1.f, po0.x + po0.y + po0.z + po0.w + po1.x + po1.y + po1.z + po1.w);

        char* rowE = smc + P_B + (t0 + g) * PSTRIDE;
        char* rowO = smc + P_B + (t0 + g + 8) * PSTRIDE;
        #pragma unroll
        for (int o = 0; o < 4; o++) {
            if (o < nOct) {
                int c = n0 + 8 * o + q2;
                float2 d = *(float2*)&sDec[c];
                *(__half2*)(rowE + c * 2) =
                    __floats2half2_rn(ev[4 * o + 0] * invE * d.x, ev[4 * o + 1] * invE * d.y);
                *(__half2*)(rowO + c * 2) =
                    __floats2half2_rn(ev[4 * o + 2] * invO * d.x, ev[4 * o + 3] * invO * d.y);
            }
        }
    }
    __syncthreads();

    // ---------------- Phase E: context = P @ seq via MMA (32 tiles over 28 warps) ----------------
    {
        const uint32_t rowSel = (uint32_t)((lane & 7) + ((lane >> 3) & 1) * 8);
        const int rr = lane >> 2, cc = (lane & 3) * 2;
        float* gout = out + (size_t)b * TQ * DD;

        for (int tile = warp; tile < 32; tile += 28) {
            const int t0e = (tile >> 3) * 16;
            const int d0  = (tile & 7) * 8;
            const uint32_t pBase = sbase + P_B + (uint32_t)((t0e + rowSel) * PSTRIDE) + (uint32_t)((lane >> 4) * 16);
            const uint32_t kBase = sbase + SEQK_B + rowSel * ASTRIDE + (uint32_t)(d0 * 2);

            float accA[4] = {0.f, 0.f, 0.f, 0.f};
            #pragma unroll
            for (int kc = 0; kc < 13; kc++) {
                uint32_t a[4], bb2[2];
                ldsm_x4(a, pBase + (uint32_t)(kc * 32));
                ldsm_x2t(bb2, kBase + (uint32_t)(kc * 16) * ASTRIDE);
                mma_f16(accA, a, bb2[0], bb2[1]);
            }
            *(float2*)(gout + (t0e + rr) * 64 + d0 + cc)     = make_float2(accA[0], accA[1]);
            *(float2*)(gout + (t0e + rr + 8) * 64 + d0 + cc) = make_float2(accA[2], accA[3]);
        }
    }
}

extern "C" void kernel_launch(void* const* d_in, const int* in_sizes, int n_in,
                              void* d_out, int out_size)
{
    const float* seq    = (const float*)d_in[0];
    const float* dtn    = (const float*)d_in[1];
    const float* target = (const float*)d_in[2];
    const int*   vmask  = (const int*)  d_in[3];
    const float* fr     = (const float*)d_in[4];
    const float* fi     = (const float*)d_in[5];
    const float* Aw     = (const float*)d_in[6];
    const float* Ab     = (const float*)d_in[7];
    const float* Aout   = (const float*)d_in[8];
    float* out = (float*)d_out;

    cudaFuncSetAttribute(fta_kernel, cudaFuncAttributeMaxDynamicSharedMemorySize, SMEM_TOTAL_B);
    fta_kernel<<<BB, NTHREADS, SMEM_TOTAL_B>>>(seq, dtn, target, vmask, fr, fi, Aw, Ab, Aout, out);
}

// round 13
// speedup vs baseline: 1.0298x; 1.0028x over previous
#include <cuda_runtime.h>
#include <cuda_fp16.h>
#include <cstdint>

#define BB 128
#define TQ 64
#define TK 200
#define TKP 224
#define DD 64
#define HH 10
#define NTHREADS 896

#define ASTRIDE 144            // A / SEQK row stride bytes (72 fp16)
#define PSTRIDE 432            // P row stride bytes (216 fp16)

// ---- smem byte offsets ----
#define SEQK_B   0             // fp16 seq k-major [224][144B]         32,256
#define ABUF_B   32256         // fp16 A[10][64t][144B]                92,160
#define P_B      124416        // fp16 P [64t][432B]                   27,648
#define TGT_B    152064        // float [64][65]                       16,640
#define AW_B     168704        // float [10][64]                        2,560
#define DEC_B    171264        // float [224]                             896
#define VAL_B    172160        // float [224]                             896
#define AB_B     173056        // float [16]
#define AO_B     173120        // float [16]
#define FR_B     173184        // float [64]
#define FI_B     173440        // float [64]
#define PART_B   173696        // float [64][8] row partial sums        2,048
#define SMEM_TOTAL_B 175744

static __device__ __forceinline__ uint32_t smem_u32(const void* p) {
    uint32_t a;
    asm("{ .reg .u64 t; cvta.to.shared.u64 t, %1; cvt.u32.u64 %0, t; }" : "=r"(a) : "l"(p));
    return a;
}
static __device__ __forceinline__ void ldsm_x4(uint32_t* r, uint32_t addr) {
    asm volatile("ldmatrix.sync.aligned.m8n8.x4.shared.b16 {%0,%1,%2,%3}, [%4];"
                 : "=r"(r[0]), "=r"(r[1]), "=r"(r[2]), "=r"(r[3]) : "r"(addr));
}
static __device__ __forceinline__ void ldsm_x4t(uint32_t* r, uint32_t addr) {
    asm volatile("ldmatrix.sync.aligned.m8n8.x4.trans.shared.b16 {%0,%1,%2,%3}, [%4];"
                 : "=r"(r[0]), "=r"(r[1]), "=r"(r[2]), "=r"(r[3]) : "r"(addr));
}
static __device__ __forceinline__ void ldsm_x2(uint32_t* r, uint32_t addr) {
    asm volatile("ldmatrix.sync.aligned.m8n8.x2.shared.b16 {%0,%1}, [%2];"
                 : "=r"(r[0]), "=r"(r[1]) : "r"(addr));
}
static __device__ __forceinline__ void ldsm_x2t(uint32_t* r, uint32_t addr) {
    asm volatile("ldmatrix.sync.aligned.m8n8.x2.trans.shared.b16 {%0,%1}, [%2];"
                 : "=r"(r[0]), "=r"(r[1]) : "r"(addr));
}
static __device__ __forceinline__ void mma_f16(float* c, const uint32_t* a, uint32_t b0, uint32_t b1) {
    asm volatile("mma.sync.aligned.m16n8k16.row.col.f32.f16.f16.f32 "
                 "{%0,%1,%2,%3}, {%4,%5,%6,%7}, {%8,%9}, {%0,%1,%2,%3};"
                 : "+f"(c[0]), "+f"(c[1]), "+f"(c[2]), "+f"(c[3])
                 : "r"(a[0]), "r"(a[1]), "r"(a[2]), "r"(a[3]), "r"(b0), "r"(b1));
}
static __device__ __forceinline__ float htanh(float x) {
    float y; asm("tanh.approx.f32 %0, %1;" : "=f"(y) : "f"(x)); return y;
}

__global__ __launch_bounds__(NTHREADS, 1)
void fta_kernel(const float* __restrict__ seq,
                const float* __restrict__ dtn,
                const float* __restrict__ target,
                const int*   __restrict__ vmask,
                const float* __restrict__ fr,
                const float* __restrict__ fi,
                const float* __restrict__ Aw,
                const float* __restrict__ Ab,
                const float* __restrict__ Aout,
                float* __restrict__ out)
{
    extern __shared__ char smc[];
    const uint32_t sbase = smem_u32(smc);
    float* sTgt  = (float*)(smc + TGT_B);
    float* sAw   = (float*)(smc + AW_B);
    float* sDec  = (float*)(smc + DEC_B);
    float* sVal  = (float*)(smc + VAL_B);
    float* sAb   = (float*)(smc + AB_B);
    float* sAo   = (float*)(smc + AO_B);
    float* sFr   = (float*)(smc + FR_B);
    float* sFi   = (float*)(smc + FI_B);
    float* sPart = (float*)(smc + PART_B);

    const int b    = blockIdx.x;
    const int tid  = threadIdx.x;
    const int lane = tid & 31;
    const int warp = tid >> 5;

    // ---------------- Phase A: gmem -> smem (SEQK only; no transpose) ----------------
    {
        const float4* g4 = (const float4*)(seq + (size_t)b * TK * DD);
        #pragma unroll
        for (int n = 0; n < TKP * 16 / NTHREADS; n++) {    // 4 iters
            int i = tid + n * NTHREADS;
            int k = i >> 4, d4 = i & 15;
            float4 v = make_float4(0.f, 0.f, 0.f, 0.f);
            if (k < TK) v = g4[k * 16 + d4];
            *(__half2*)(smc + SEQK_B + k * ASTRIDE + d4 * 8)     = __floats2half2_rn(v.x, v.y);
            *(__half2*)(smc + SEQK_B + k * ASTRIDE + d4 * 8 + 4) = __floats2half2_rn(v.z, v.w);
        }
        const float* gT = target + (size_t)b * TQ * DD;
        for (int i = tid; i < TQ * DD; i += NTHREADS) {
            int t = i >> 6, d = i & 63;
            sTgt[t * 65 + d] = gT[i];
        }
        if (tid < HH * DD) sAw[tid] = Aw[tid];
        if (tid < DD) { sFr[tid] = fr[tid]; sFi[tid] = fi[tid]; }
        if (tid < 16) {
            sAb[tid] = (tid < HH) ? Ab[tid]   : 0.f;
            sAo[tid] = (tid < HH) ? Aout[tid] : 0.f;
        }
        if (tid < 512) {
            sPart[tid] = 0.f;                              // zero partials (incl. pad col 7)
            // zero P columns 200-215 (bytes 400..431) for phase E's 13th k-chunk
            int row = tid >> 3, off = 400 + (tid & 7) * 4;
            *(uint32_t*)(smc + P_B + row * PSTRIDE + off) = 0u;
        }
    }
    __syncthreads();

    // ---------------- Phase B: Fourier decay + build ALL 10 A tiles ----------------
    if (tid < TKP) {
        float dec = 0.f, val = 0.f;
        if (tid < TK) {
            const int   m  = vmask[b * TK + tid];
            const float dt = dtn[b * TK + tid];
            const float th = (3.14159265358979323846f / 63.f) * dt;
            float acc = 0.f;
            #pragma unroll 8
            for (int j = 0; j < DD; j++) {
                float s, c;
                __sincosf(th * (float)j, &s, &c);
                acc = fmaf(c, sFr[j], acc);
                acc = fmaf(-s, sFi[j], acc);
            }
            float dcy = fminf(fmaxf(acc * (1.f / 128.f), 0.f), 1.f);
            if (m != 0) { dec = dcy; val = 1.f; }
        }
        sDec[tid] = dec;
        sVal[tid] = val;
    }
    for (int i = tid; i < HH * 2048; i += NTHREADS) {
        int h = i >> 11, rem = i & 2047;
        int t = rem >> 5, dp = (rem & 31) << 1;
        float a0 = sTgt[t * 65 + dp]     * sAw[h * 64 + dp];
        float a1 = sTgt[t * 65 + dp + 1] * sAw[h * 64 + dp + 1];
        *(__half2*)(smc + ABUF_B + h * 9216 + t * ASTRIDE + dp * 2) = __floats2half2_rn(a0, a1);
    }
    __syncthreads();

    // ---------------- Phase C: TN score GEMM (non-trans B), 28 warps, h-pairs share B ----------------
    const int tg  = warp / 7;                  // 0..3
    const int ng  = warp % 7;                  // 0..6
    const int t0  = tg * 16;
    const bool wide = (ng < 4);
    const int n0  = wide ? ng * 32 : 128 + (ng - 4) * 24;  // 4x32 + 3x24 = 200 cols exactly
    const int g   = lane >> 2;
    const int q2  = (lane & 3) * 2;

    float sc[16];
    {
        const uint32_t rowSel = (uint32_t)((lane & 7) + ((lane >> 3) & 1) * 8);
        const uint32_t aBase  = sbase + ABUF_B + (uint32_t)((t0 + rowSel) * ASTRIDE)
                              + (uint32_t)((lane >> 4) * 16);
        const uint32_t bRow   = (uint32_t)(n0 + (lane & 7) + ((lane >> 4) << 3));
        const uint32_t bBase  = sbase + SEQK_B + bRow * ASTRIDE + (uint32_t)(((lane >> 3) & 1) * 16);
        const uint32_t b2Base = sbase + SEQK_B + (uint32_t)((n0 + 16 + (lane & 7)) * ASTRIDE)
                              + (uint32_t)(((lane >> 3) & 1) * 16);

        #pragma unroll
        for (int i = 0; i < 16; i++) sc[i] = 0.f;

        for (int h = 0; h < HH; h += 2) {
            const float ab0 = sAb[h], ab1 = sAb[h + 1];
            float acc0[16], acc1[16];
            #pragma unroll
            for (int i = 0; i < 16; i++) { acc0[i] = ab0; acc1[i] = ab1; }  // bias folded in

            const uint32_t aA0 = aBase + (uint32_t)(h * 9216);
            const uint32_t aA1 = aA0 + 9216;
            #pragma unroll
            for (int ks = 0; ks < 4; ks++) {
                const uint32_t d0b = (uint32_t)(ks * 32);
                uint32_t bb[8];
                ldsm_x4(bb, bBase + d0b);                       // tokens n0..n0+15
                if (wide) ldsm_x4(bb + 4, bBase + 2304 + d0b);  // tokens n0+16..n0+31
                else      ldsm_x2(bb + 4, b2Base + d0b);        // tokens n0+16..n0+23
                uint32_t af0[4], af1[4];
                ldsm_x4(af0, aA0 + d0b);
                ldsm_x4(af1, aA1 + d0b);
                mma_f16(acc0 + 0, af0, bb[0], bb[1]);
                mma_f16(acc0 + 4, af0, bb[2], bb[3]);
                mma_f16(acc0 + 8, af0, bb[4], bb[5]);
                mma_f16(acc1 + 0, af1, bb[0], bb[1]);
                mma_f16(acc1 + 4, af1, bb[2], bb[3]);
                mma_f16(acc1 + 8, af1, bb[4], bb[5]);
                if (wide) {
                    mma_f16(acc0 + 12, af0, bb[6], bb[7]);
                    mma_f16(acc1 + 12, af1, bb[6], bb[7]);
                }
            }

            // epilogue: sc += ao * tanh(acc)  (bias already in acc; no scaling)
            const float ao0 = sAo[h], ao1 = sAo[h + 1];
            const int nel = wide ? 16 : 12;
            #pragma unroll
            for (int i = 0; i < 16; i++) {
                if (i < nel) {
                    sc[i] = fmaf(ao0, htanh(acc0[i]), sc[i]);
                    sc[i] = fmaf(ao1, htanh(acc1[i]), sc[i]);
                }
            }
        }
    }

    // ---------------- Phase D: softmax + decay from registers -> fp16 P ----------------
    {
        const int nOct = wide ? 4 : 3;
        float ev[16];
        float se = 0.f, so = 0.f;
        #pragma unroll
        for (int o = 0; o < 4; o++) {
            if (o < nOct) {
                int c = n0 + 8 * o + q2;
                float2 v = *(float2*)&sVal[c];
                float e0 = v.x * __expf(sc[4 * o + 0]);
                float e1 = v.y * __expf(sc[4 * o + 1]);
                float e2 = v.x * __expf(sc[4 * o + 2]);
                float e3 = v.y * __expf(sc[4 * o + 3]);
                ev[4 * o + 0] = e0; ev[4 * o + 1] = e1;
                ev[4 * o + 2] = e2; ev[4 * o + 3] = e3;
                se += e0 + e1;
                so += e2 + e3;
            }
        }
        se += __shfl_xor_sync(0xffffffffu, se, 1);
        se += __shfl_xor_sync(0xffffffffu, se, 2);
        so += __shfl_xor_sync(0xffffffffu, so, 1);
        so += __shfl_xor_sync(0xffffffffu, so, 2);
        if ((lane & 3) == 0) {
            sPart[(t0 + g) * 8 + ng]     = se;
            sPart[(t0 + g + 8) * 8 + ng] = so;
        }
        __syncthreads();   // phase C smem reads done + partials visible

        float4 pe0 = ((float4*)&sPart[(t0 + g) * 8])[0];
        float4 pe1 = ((float4*)&sPart[(t0 + g) * 8])[1];
        float4 po0 = ((float4*)&sPart[(t0 + g + 8) * 8])[0];
        float4 po1 = ((float4*)&sPart[(t0 + g + 8) * 8])[1];
        const float invE = __fdividef(1.f, pe0.x + pe0.y + pe0.z + pe0.w + pe1.x + pe1.y + pe1.z + pe1.w);
        const float invO = __fdividef(1.f, po0.x + po0.y + po0.z + po0.w + po1.x + po1.y + po1.z + po1.w);

        char* rowE = smc + P_B + (t0 + g) * PSTRIDE;
        char* rowO = smc + P_B + (t0 + g + 8) * PSTRIDE;
        #pragma unroll
        for (int o = 0; o < 4; o++) {
            if (o < nOct) {
                int c = n0 + 8 * o + q2;
                float2 d = *(float2*)&sDec[c];
                *(__half2*)(rowE + c * 2) =
                    __floats2half2_rn(ev[4 * o + 0] * invE * d.x, ev[4 * o + 1] * invE * d.y);
                *(__half2*)(rowO + c * 2) =
                    __floats2half2_rn(ev[4 * o + 2] * invO * d.x, ev[4 * o + 3] * invO * d.y);
            }
        }
    }
    __syncthreads();

    // ---------------- Phase E: context = P @ seq via MMA (32 tiles over 28 warps) ----------------
    {
        const uint32_t rowSel = (uint32_t)((lane & 7) + ((lane >> 3) & 1) * 8);
        const int rr = lane >> 2, cc = (lane & 3) * 2;
        float* gout = out + (size_t)b * TQ * DD;

        for (int tile = warp; tile < 32; tile += 28) {
            const int t0e = (tile >> 3) * 16;
            const int d0  = (tile & 7) * 8;
            const uint32_t pBase = sbase + P_B + (uint32_t)((t0e + rowSel) * PSTRIDE) + (uint32_t)((lane >> 4) * 16);
            const uint32_t kBase = sbase + SEQK_B + rowSel * ASTRIDE + (uint32_t)(d0 * 2);

            float accA[4] = {0.f, 0.f, 0.f, 0.f};
            #pragma unroll
            for (int kc = 0; kc < 13; kc++) {
                uint32_t a[4], bb2[2];
                ldsm_x4(a, pBase + (uint32_t)(kc * 32));
                ldsm_x2t(bb2, kBase + (uint32_t)(kc * 16) * ASTRIDE);
                mma_f16(accA, a, bb2[0], bb2[1]);
            }
            *(float2*)(gout + (t0e + rr) * 64 + d0 + cc)     = make_float2(accA[0], accA[1]);
            *(float2*)(gout + (t0e + rr + 8) * 64 + d0 + cc) = make_float2(accA[2], accA[3]);
        }
    }
}

extern "C" void kernel_launch(void* const* d_in, const int* in_sizes, int n_in,
                              void* d_out, int out_size)
{
    const float* seq    = (const float*)d_in[0];
    const float* dtn    = (const float*)d_in[1];
    const float* target = (const float*)d_in[2];
    const int*   vmask  = (const int*)  d_in[3];
    const float* fr     = (const float*)d_in[4];
    const float* fi     = (const float*)d_in[5];
    const float* Aw     = (const float*)d_in[6];
    const float* Ab     = (const float*)d_in[7];
    const float* Aout   = (const float*)d_in[8];
    float* out = (float*)d_out;

    cudaFuncSetAttribute(fta_kernel, cudaFuncAttributeMaxDynamicSharedMemorySize, SMEM_TOTAL_B);
    fta_kernel<<<BB, NTHREADS, SMEM_TOTAL_B>>>(seq, dtn, target, vmask, fr, fi, Aw, Ab, Aout, out);
}

// round 14
// speedup vs baseline: 1.0692x; 1.0383x over previous
#include <cuda_runtime.h>
#include <cuda_fp16.h>
#include <cstdint>

#define BB 128
#define TQ 64
#define TK 200
#define TKP 224
#define DD 64
#define HH 10
#define NTHREADS 896

#define ASTRIDE 144            // A / SEQK row stride bytes (72 fp16)
#define PSTRIDE 432            // P row stride bytes (216 fp16)

// ---- smem byte offsets ----
#define SEQK_B   0             // fp16 seq k-major [224][144B]         32,256
#define ABUF_B   32256         // fp16 A[10][64t][144B]                92,160
#define P_B      124416        // fp16 P [64t][432B]                   27,648
#define TGT_B    152064        // float [64][65]                       16,640
#define AW_B     168704        // float [10][64]                        2,560
#define DEC_B    171264        // float [224]                             896
#define VAL_B    172160        // float [224]                             896
#define AB_B     173056        // float [16]
#define AO_B     173120        // float [16]
#define FR_B     173184        // float [64]
#define FI_B     173440        // float [64]
#define PART_B   173696        // float [64][8] row partial sums        2,048
#define SMEM_TOTAL_B 175744

static __device__ __forceinline__ uint32_t smem_u32(const void* p) {
    uint32_t a;
    asm("{ .reg .u64 t; cvta.to.shared.u64 t, %1; cvt.u32.u64 %0, t; }" : "=r"(a) : "l"(p));
    return a;
}
static __device__ __forceinline__ void ldsm_x4(uint32_t* r, uint32_t addr) {
    asm volatile("ldmatrix.sync.aligned.m8n8.x4.shared.b16 {%0,%1,%2,%3}, [%4];"
                 : "=r"(r[0]), "=r"(r[1]), "=r"(r[2]), "=r"(r[3]) : "r"(addr));
}
static __device__ __forceinline__ void ldsm_x2(uint32_t* r, uint32_t addr) {
    asm volatile("ldmatrix.sync.aligned.m8n8.x2.shared.b16 {%0,%1}, [%2];"
                 : "=r"(r[0]), "=r"(r[1]) : "r"(addr));
}
static __device__ __forceinline__ void ldsm_x2t(uint32_t* r, uint32_t addr) {
    asm volatile("ldmatrix.sync.aligned.m8n8.x2.trans.shared.b16 {%0,%1}, [%2];"
                 : "=r"(r[0]), "=r"(r[1]) : "r"(addr));
}
static __device__ __forceinline__ void mma_f16(float* c, const uint32_t* a, uint32_t b0, uint32_t b1) {
    asm volatile("mma.sync.aligned.m16n8k16.row.col.f32.f16.f16.f32 "
                 "{%0,%1,%2,%3}, {%4,%5,%6,%7}, {%8,%9}, {%0,%1,%2,%3};"
                 : "+f"(c[0]), "+f"(c[1]), "+f"(c[2]), "+f"(c[3])
                 : "r"(a[0]), "r"(a[1]), "r"(a[2]), "r"(a[3]), "r"(b0), "r"(b1));
}
// pack two f32 into f16x2: lo = x0, hi = x1
static __device__ __forceinline__ uint32_t pack_h2(float x0, float x1) {
    uint32_t r;
    asm("cvt.rn.f16x2.f32 %0, %1, %2;" : "=r"(r) : "f"(x1), "f"(x0));
    return r;
}
static __device__ __forceinline__ uint32_t tanh2(uint32_t x) {
    uint32_t y; asm("tanh.approx.f16x2 %0, %1;" : "=r"(y) : "r"(x)); return y;
}

__global__ __launch_bounds__(NTHREADS, 1)
void fta_kernel(const float* __restrict__ seq,
                const float* __restrict__ dtn,
                const float* __restrict__ target,
                const int*   __restrict__ vmask,
                const float* __restrict__ fr,
                const float* __restrict__ fi,
                const float* __restrict__ Aw,
                const float* __restrict__ Ab,
                const float* __restrict__ Aout,
                float* __restrict__ out)
{
    extern __shared__ char smc[];
    const uint32_t sbase = smem_u32(smc);
    float* sTgt  = (float*)(smc + TGT_B);
    float* sAw   = (float*)(smc + AW_B);
    float* sDec  = (float*)(smc + DEC_B);
    float* sVal  = (float*)(smc + VAL_B);
    float* sAb   = (float*)(smc + AB_B);
    float* sAo   = (float*)(smc + AO_B);
    float* sFr   = (float*)(smc + FR_B);
    float* sFi   = (float*)(smc + FI_B);
    float* sPart = (float*)(smc + PART_B);

    const int b    = blockIdx.x;
    const int tid  = threadIdx.x;
    const int lane = tid & 31;
    const int warp = tid >> 5;

    // ---------------- Phase A: gmem -> smem (SEQK only; no transpose) ----------------
    {
        const float4* g4 = (const float4*)(seq + (size_t)b * TK * DD);
        #pragma unroll
        for (int n = 0; n < TKP * 16 / NTHREADS; n++) {    // 4 iters
            int i = tid + n * NTHREADS;
            int k = i >> 4, d4 = i & 15;
            float4 v = make_float4(0.f, 0.f, 0.f, 0.f);
            if (k < TK) v = g4[k * 16 + d4];
            *(__half2*)(smc + SEQK_B + k * ASTRIDE + d4 * 8)     = __floats2half2_rn(v.x, v.y);
            *(__half2*)(smc + SEQK_B + k * ASTRIDE + d4 * 8 + 4) = __floats2half2_rn(v.z, v.w);
        }
        const float* gT = target + (size_t)b * TQ * DD;
        for (int i = tid; i < TQ * DD; i += NTHREADS) {
            int t = i >> 6, d = i & 63;
            sTgt[t * 65 + d] = gT[i];
        }
        if (tid < HH * DD) sAw[tid] = Aw[tid];
        if (tid < DD) { sFr[tid] = fr[tid]; sFi[tid] = fi[tid]; }
        if (tid < 16) {
            sAb[tid] = (tid < HH) ? Ab[tid]   : 0.f;
            sAo[tid] = (tid < HH) ? Aout[tid] : 0.f;
        }
        if (tid < 512) {
            sPart[tid] = 0.f;                              // zero partials (incl. pad col 7)
            // zero P columns 200-215 (bytes 400..431) for phase E's 13th k-chunk
            int row = tid >> 3, off = 400 + (tid & 7) * 4;
            *(uint32_t*)(smc + P_B + row * PSTRIDE + off) = 0u;
        }
    }
    __syncthreads();

    // ---------------- Phase B: Fourier decay + build ALL 10 A tiles ----------------
    if (tid < TKP) {
        float dec = 0.f, val = 0.f;
        if (tid < TK) {
            const int   m  = vmask[b * TK + tid];
            const float dt = dtn[b * TK + tid];
            const float th = (3.14159265358979323846f / 63.f) * dt;
            float acc = 0.f;
            #pragma unroll 8
            for (int j = 0; j < DD; j++) {
                float s, c;
                __sincosf(th * (float)j, &s, &c);
                acc = fmaf(c, sFr[j], acc);
                acc = fmaf(-s, sFi[j], acc);
            }
            float dcy = fminf(fmaxf(acc * (1.f / 128.f), 0.f), 1.f);
            if (m != 0) { dec = dcy; val = 1.f; }
        }
        sDec[tid] = dec;
        sVal[tid] = val;
    }
    for (int i = tid; i < HH * 2048; i += NTHREADS) {
        int h = i >> 11, rem = i & 2047;
        int t = rem >> 5, dp = (rem & 31) << 1;
        float a0 = sTgt[t * 65 + dp]     * sAw[h * 64 + dp];
        float a1 = sTgt[t * 65 + dp + 1] * sAw[h * 64 + dp + 1];
        *(__half2*)(smc + ABUF_B + h * 9216 + t * ASTRIDE + dp * 2) = __floats2half2_rn(a0, a1);
    }
    __syncthreads();

    // ---------------- Phase C: TN score GEMM (non-trans B), 28 warps, h-pairs share B ----------------
    const int tg  = warp / 7;                  // 0..3
    const int ng  = warp % 7;                  // 0..6
    const int t0  = tg * 16;
    const bool wide = (ng < 4);
    const int n0  = wide ? ng * 32 : 128 + (ng - 4) * 24;  // 4x32 + 3x24 = 200 cols exactly
    const int g   = lane >> 2;
    const int q2  = (lane & 3) * 2;

    __half2 sc2[8];                            // packed (col c, col c+1) per (octet, row-half)
    {
        const uint32_t rowSel = (uint32_t)((lane & 7) + ((lane >> 3) & 1) * 8);
        const uint32_t aBase  = sbase + ABUF_B + (uint32_t)((t0 + rowSel) * ASTRIDE)
                              + (uint32_t)((lane >> 4) * 16);
        const uint32_t bRow   = (uint32_t)(n0 + (lane & 7) + ((lane >> 4) << 3));
        const uint32_t bBase  = sbase + SEQK_B + bRow * ASTRIDE + (uint32_t)(((lane >> 3) & 1) * 16);
        const uint32_t b2Base = sbase + SEQK_B + (uint32_t)((n0 + 16 + (lane & 7)) * ASTRIDE)
                              + (uint32_t)(((lane >> 3) & 1) * 16);

        #pragma unroll
        for (int i = 0; i < 8; i++) sc2[i] = __float2half2_rn(0.f);

        for (int h = 0; h < HH; h += 2) {
            const float ab0 = sAb[h], ab1 = sAb[h + 1];
            float acc0[16], acc1[16];
            #pragma unroll
            for (int i = 0; i < 16; i++) { acc0[i] = ab0; acc1[i] = ab1; }  // bias folded in

            const uint32_t aA0 = aBase + (uint32_t)(h * 9216);
            const uint32_t aA1 = aA0 + 9216;
            #pragma unroll
            for (int ks = 0; ks < 4; ks++) {
                const uint32_t d0b = (uint32_t)(ks * 32);
                uint32_t bb[8];
                ldsm_x4(bb, bBase + d0b);                       // tokens n0..n0+15
                if (wide) ldsm_x4(bb + 4, bBase + 2304 + d0b);  // tokens n0+16..n0+31
                else      ldsm_x2(bb + 4, b2Base + d0b);        // tokens n0+16..n0+23
                uint32_t af0[4], af1[4];
                ldsm_x4(af0, aA0 + d0b);
                ldsm_x4(af1, aA1 + d0b);
                mma_f16(acc0 + 0, af0, bb[0], bb[1]);
                mma_f16(acc0 + 4, af0, bb[2], bb[3]);
                mma_f16(acc0 + 8, af0, bb[4], bb[5]);
                mma_f16(acc1 + 0, af1, bb[0], bb[1]);
                mma_f16(acc1 + 4, af1, bb[2], bb[3]);
                mma_f16(acc1 + 8, af1, bb[4], bb[5]);
                if (wide) {
                    mma_f16(acc0 + 12, af0, bb[6], bb[7]);
                    mma_f16(acc1 + 12, af1, bb[6], bb[7]);
                }
            }

            // epilogue: sc2 += ao * tanh(acc)  — 2 elems per MUFU op
            const __half2 ao0h = __float2half2_rn(sAo[h]);
            const __half2 ao1h = __float2half2_rn(sAo[h + 1]);
            const int npair = wide ? 8 : 6;
            #pragma unroll
            for (int i = 0; i < 8; i++) {
                if (i < npair) {
                    uint32_t t0p = tanh2(pack_h2(acc0[2 * i], acc0[2 * i + 1]));
                    sc2[i] = __hfma2(ao0h, *(__half2*)&t0p, sc2[i]);
                    uint32_t t1p = tanh2(pack_h2(acc1[2 * i], acc1[2 * i + 1]));
                    sc2[i] = __hfma2(ao1h, *(__half2*)&t1p, sc2[i]);
                }
            }
        }
    }

    // ---------------- Phase D: softmax + decay -> fp16 P ----------------
    {
        const int nOct = wide ? 4 : 3;
        float ev[16];
        float se = 0.f, so = 0.f;
        #pragma unroll
        for (int o = 0; o < 4; o++) {
            if (o < nOct) {
                int c = n0 + 8 * o + q2;
                float2 v = *(float2*)&sVal[c];
                float s0 = __low2float(sc2[2 * o]);
                float s1 = __high2float(sc2[2 * o]);
                float s2 = __low2float(sc2[2 * o + 1]);
                float s3 = __high2float(sc2[2 * o + 1]);
                float e0 = v.x * __expf(s0);
                float e1 = v.y * __expf(s1);
                float e2 = v.x * __expf(s2);
                float e3 = v.y * __expf(s3);
                ev[4 * o + 0] = e0; ev[4 * o + 1] = e1;
                ev[4 * o + 2] = e2; ev[4 * o + 3] = e3;
                se += e0 + e1;
                so += e2 + e3;
            }
        }
        se += __shfl_xor_sync(0xffffffffu, se, 1);
        se += __shfl_xor_sync(0xffffffffu, se, 2);
        so += __shfl_xor_sync(0xffffffffu, so, 1);
        so += __shfl_xor_sync(0xffffffffu, so, 2);
        if ((lane & 3) == 0) {
            sPart[(t0 + g) * 8 + ng]     = se;
            sPart[(t0 + g + 8) * 8 + ng] = so;
        }
        __syncthreads();   // phase C smem reads done + partials visible

        float4 pe0 = ((float4*)&sPart[(t0 + g) * 8])[0];
        float4 pe1 = ((float4*)&sPart[(t0 + g) * 8])[1];
        float4 po0 = ((float4*)&sPart[(t0 + g + 8) * 8])[0];
        float4 po1 = ((float4*)&sPart[(t0 + g + 8) * 8])[1];
        const float invE = __fdividef(1.f, pe0.x + pe0.y + pe0.z + pe0.w + pe1.x + pe1.y + pe1.z + pe1.w);
        const float invO = __fdividef(1.f, po0.x + po0.y + po0.z + po0.w + po1.x + po1.y + po1.z + po1.w);

        char* rowE = smc + P_B + (t0 + g) * PSTRIDE;
        char* rowO = smc + P_B + (t0 + g + 8) * PSTRIDE;
        #pragma unroll
        for (int o = 0; o < 4; o++) {
            if (o < nOct) {
                int c = n0 + 8 * o + q2;
                float2 d = *(float2*)&sDec[c];
                *(__half2*)(rowE + c * 2) =
                    __floats2half2_rn(ev[4 * o + 0] * invE * d.x, ev[4 * o + 1] * invE * d.y);
                *(__half2*)(rowO + c * 2) =
                    __floats2half2_rn(ev[4 * o + 2] * invO * d.x, ev[4 * o + 3] * invO * d.y);
            }
        }
    }
    __syncthreads();

    // ---------------- Phase E: context = P @ seq via MMA (32 tiles over 28 warps) ----------------
    {
        const uint32_t rowSel = (uint32_t)((lane & 7) + ((lane >> 3) & 1) * 8);
        const int rr = lane >> 2, cc = (lane & 3) * 2;
        float* gout = out + (size_t)b * TQ * DD;

        for (int tile = warp; tile < 32; tile += 28) {
            const int t0e = (tile >> 3) * 16;
            const int d0  = (tile & 7) * 8;
            const uint32_t pBase = sbase + P_B + (uint32_t)((t0e + rowSel) * PSTRIDE) + (uint32_t)((lane >> 4) * 16);
            const uint32_t kBase = sbase + SEQK_B + rowSel * ASTRIDE + (uint32_t)(d0 * 2);

            float accA[4] = {0.f, 0.f, 0.f, 0.f};
            #pragma unroll
            for (int kc = 0; kc < 13; kc++) {
                uint32_t a[4], bb2[2];
                ldsm_x4(a, pBase + (uint32_t)(kc * 32));
                ldsm_x2t(bb2, kBase + (uint32_t)(kc * 16) * ASTRIDE);
                mma_f16(accA, a, bb2[0], bb2[1]);
            }
            *(float2*)(gout + (t0e + rr) * 64 + d0 + cc)     = make_float2(accA[0], accA[1]);
            *(float2*)(gout + (t0e + rr + 8) * 64 + d0 + cc) = make_float2(accA[2], accA[3]);
        }
    }
}

extern "C" void kernel_launch(void* const* d_in, const int* in_sizes, int n_in,
                              void* d_out, int out_size)
{
    const float* seq    = (const float*)d_in[0];
    const float* dtn    = (const float*)d_in[1];
    const float* target = (const float*)d_in[2];
    const int*   vmask  = (const int*)  d_in[3];
    const float* fr     = (const float*)d_in[4];
    const float* fi     = (const float*)d_in[5];
    const float* Aw     = (const float*)d_in[6];
    const float* Ab     = (const float*)d_in[7];
    const float* Aout   = (const float*)d_in[8];
    float* out = (float*)d_out;

    cudaFuncSetAttribute(fta_kernel, cudaFuncAttributeMaxDynamicSharedMemorySize, SMEM_TOTAL_B);
    fta_kernel<<<BB, NTHREADS, SMEM_TOTAL_B>>>(seq, dtn, target, vmask, fr, fi, Aw, Ab, Aout, out);
}

// round 15
// speedup vs baseline: 1.0934x; 1.0226x over previous
#include <cuda_runtime.h>
#include <cuda_fp16.h>
#include <cstdint>

#define BB 128
#define TQ 64
#define TK 200
#define TKP 224
#define DD 64
#define HH 10
#define NTHREADS 896

#define ASTRIDE 144            // A / SEQK row stride bytes (72 fp16)
#define PSTRIDE 432            // P row stride bytes (216 fp16)

// ---- smem byte offsets ----
#define SEQK_B   0             // fp16 seq k-major [224][144B]         32,256
#define ABUF_B   32256         // fp16 A[10][64t][144B]                92,160
#define P_B      124416        // fp16 P [64t][432B]                   27,648
#define TGT_B    152064        // float [64][68]                       17,408
#define AW_B     169472        // float [10][64]                        2,560
#define DEC_B    172032        // float [224]                             896
#define VAL_B    172928        // float [224]                             896
#define AB_B     173824        // float [16]
#define AO_B     173888        // float [16]
#define FR_B     173952        // float [64]
#define FI_B     174208        // float [64]
#define PART_B   174464        // float [64][8] row partial sums        2,048
#define SMEM_TOTAL_B 176512

static __device__ __forceinline__ uint32_t smem_u32(const void* p) {
    uint32_t a;
    asm("{ .reg .u64 t; cvta.to.shared.u64 t, %1; cvt.u32.u64 %0, t; }" : "=r"(a) : "l"(p));
    return a;
}
static __device__ __forceinline__ void ldsm_x4(uint32_t* r, uint32_t addr) {
    asm volatile("ldmatrix.sync.aligned.m8n8.x4.shared.b16 {%0,%1,%2,%3}, [%4];"
                 : "=r"(r[0]), "=r"(r[1]), "=r"(r[2]), "=r"(r[3]) : "r"(addr));
}
static __device__ __forceinline__ void ldsm_x4t(uint32_t* r, uint32_t addr) {
    asm volatile("ldmatrix.sync.aligned.m8n8.x4.trans.shared.b16 {%0,%1,%2,%3}, [%4];"
                 : "=r"(r[0]), "=r"(r[1]), "=r"(r[2]), "=r"(r[3]) : "r"(addr));
}
static __device__ __forceinline__ void ldsm_x2(uint32_t* r, uint32_t addr) {
    asm volatile("ldmatrix.sync.aligned.m8n8.x2.shared.b16 {%0,%1}, [%2];"
                 : "=r"(r[0]), "=r"(r[1]) : "r"(addr));
}
static __device__ __forceinline__ void ldsm_x2t(uint32_t* r, uint32_t addr) {
    asm volatile("ldmatrix.sync.aligned.m8n8.x2.trans.shared.b16 {%0,%1}, [%2];"
                 : "=r"(r[0]), "=r"(r[1]) : "r"(addr));
}
static __device__ __forceinline__ void mma_f16(float* c, const uint32_t* a, uint32_t b0, uint32_t b1) {
    asm volatile("mma.sync.aligned.m16n8k16.row.col.f32.f16.f16.f32 "
                 "{%0,%1,%2,%3}, {%4,%5,%6,%7}, {%8,%9}, {%0,%1,%2,%3};"
                 : "+f"(c[0]), "+f"(c[1]), "+f"(c[2]), "+f"(c[3])
                 : "r"(a[0]), "r"(a[1]), "r"(a[2]), "r"(a[3]), "r"(b0), "r"(b1));
}
// pack two f32 into f16x2: lo = x0, hi = x1
static __device__ __forceinline__ uint32_t pack_h2(float x0, float x1) {
    uint32_t r;
    asm("cvt.rn.f16x2.f32 %0, %1, %2;" : "=r"(r) : "f"(x1), "f"(x0));
    return r;
}
static __device__ __forceinline__ uint32_t tanh2(uint32_t x) {
    uint32_t y; asm("tanh.approx.f16x2 %0, %1;" : "=r"(y) : "r"(x)); return y;
}

__global__ __launch_bounds__(NTHREADS, 1)
void fta_kernel(const float* __restrict__ seq,
                const float* __restrict__ dtn,
                const float* __restrict__ target,
                const int*   __restrict__ vmask,
                const float* __restrict__ fr,
                const float* __restrict__ fi,
                const float* __restrict__ Aw,
                const float* __restrict__ Ab,
                const float* __restrict__ Aout,
                float* __restrict__ out)
{
    extern __shared__ char smc[];
    const uint32_t sbase = smem_u32(smc);
    float* sTgt  = (float*)(smc + TGT_B);
    float* sAw   = (float*)(smc + AW_B);
    float* sDec  = (float*)(smc + DEC_B);
    float* sVal  = (float*)(smc + VAL_B);
    float* sAb   = (float*)(smc + AB_B);
    float* sAo   = (float*)(smc + AO_B);
    float* sFr   = (float*)(smc + FR_B);
    float* sFi   = (float*)(smc + FI_B);
    float* sPart = (float*)(smc + PART_B);

    const int b    = blockIdx.x;
    const int tid  = threadIdx.x;
    const int lane = tid & 31;
    const int warp = tid >> 5;

    // ---------------- Phase A: gmem -> smem (SEQK + fp32 tgt, vectorized) ----------------
    {
        const float4* g4 = (const float4*)(seq + (size_t)b * TK * DD);
        #pragma unroll
        for (int n = 0; n < TKP * 16 / NTHREADS; n++) {    // 4 iters
            int i = tid + n * NTHREADS;
            int k = i >> 4, d4 = i & 15;
            float4 v = make_float4(0.f, 0.f, 0.f, 0.f);
            if (k < TK) v = g4[k * 16 + d4];
            *(__half2*)(smc + SEQK_B + k * ASTRIDE + d4 * 8)     = __floats2half2_rn(v.x, v.y);
            *(__half2*)(smc + SEQK_B + k * ASTRIDE + d4 * 8 + 4) = __floats2half2_rn(v.z, v.w);
        }
        const float4* gT4 = (const float4*)(target + (size_t)b * TQ * DD);
        for (int i = tid; i < TQ * 16; i += NTHREADS) {    // 2 iters (partial)
            int t = i >> 4, dq = (i & 15) * 4;
            *(float4*)(sTgt + t * 68 + dq) = gT4[i];
        }
        if (tid < HH * DD) sAw[tid] = Aw[tid];
        if (tid < DD) { sFr[tid] = fr[tid]; sFi[tid] = fi[tid]; }
        if (tid < 16) {
            sAb[tid] = (tid < HH) ? Ab[tid]   : 0.f;
            sAo[tid] = (tid < HH) ? Aout[tid] : 0.f;
        }
        if (tid < 512) {
            sPart[tid] = 0.f;                              // zero partials (incl. pad col 7)
            // zero P columns 200-215 (bytes 400..431) for phase E's 13th k-chunk
            int row = tid >> 3, off = 400 + (tid & 7) * 4;
            *(uint32_t*)(smc + P_B + row * PSTRIDE + off) = 0u;
        }
    }
    __syncthreads();

    // ---------------- Phase B: Fourier decay + build ALL 10 A tiles (8-wide) ----------------
    if (tid < TKP) {
        float dec = 0.f, val = 0.f;
        if (tid < TK) {
            const int   m  = vmask[b * TK + tid];
            const float dt = dtn[b * TK + tid];
            const float th = (3.14159265358979323846f / 63.f) * dt;
            float acc = 0.f;
            #pragma unroll 8
            for (int j = 0; j < DD; j++) {
                float s, c;
                __sincosf(th * (float)j, &s, &c);
                acc = fmaf(c, sFr[j], acc);
                acc = fmaf(-s, sFi[j], acc);
            }
            float dcy = fminf(fmaxf(acc * (1.f / 128.f), 0.f), 1.f);
            if (m != 0) { dec = dcy; val = 1.f; }
        }
        sDec[tid] = dec;
        sVal[tid] = val;
    }
    for (int i = tid; i < HH * 512; i += NTHREADS) {       // 6 iters (partial)
        int h = i >> 9, rem = i & 511;
        int t = rem >> 3, d8 = (rem & 7) << 3;
        const float* tg  = sTgt + t * 68 + d8;
        const float* awp = sAw + h * 64 + d8;
        float4 t0v = *(const float4*)tg, t1v = *(const float4*)(tg + 4);
        float4 w0v = *(const float4*)awp, w1v = *(const float4*)(awp + 4);
        __half2 p0 = __floats2half2_rn(t0v.x * w0v.x, t0v.y * w0v.y);
        __half2 p1 = __floats2half2_rn(t0v.z * w0v.z, t0v.w * w0v.w);
        __half2 p2 = __floats2half2_rn(t1v.x * w1v.x, t1v.y * w1v.y);
        __half2 p3 = __floats2half2_rn(t1v.z * w1v.z, t1v.w * w1v.w);
        uint4 pk = make_uint4(*(uint32_t*)&p0, *(uint32_t*)&p1, *(uint32_t*)&p2, *(uint32_t*)&p3);
        *(uint4*)(smc + ABUF_B + h * 9216 + t * ASTRIDE + d8 * 2) = pk;
    }
    __syncthreads();

    // ---------------- Phase C: TN score GEMM (non-trans B), 28 warps, h-pairs share B ----------------
    const int tg  = warp / 7;                  // 0..3
    const int ng  = warp % 7;                  // 0..6
    const int t0  = tg * 16;
    const bool wide = (ng < 4);
    const int n0  = wide ? ng * 32 : 128 + (ng - 4) * 24;  // 4x32 + 3x24 = 200 cols exactly
    const int g   = lane >> 2;
    const int q2  = (lane & 3) * 2;

    __half2 sc2[8];                            // packed (col c, col c+1) per (octet, row-half)
    {
        const uint32_t rowSel = (uint32_t)((lane & 7) + ((lane >> 3) & 1) * 8);
        const uint32_t aBase  = sbase + ABUF_B + (uint32_t)((t0 + rowSel) * ASTRIDE)
                              + (uint32_t)((lane >> 4) * 16);
        const uint32_t bRow   = (uint32_t)(n0 + (lane & 7) + ((lane >> 4) << 3));
        const uint32_t bBase  = sbase + SEQK_B + bRow * ASTRIDE + (uint32_t)(((lane >> 3) & 1) * 16);
        const uint32_t b2Base = sbase + SEQK_B + (uint32_t)((n0 + 16 + (lane & 7)) * ASTRIDE)
                              + (uint32_t)(((lane >> 3) & 1) * 16);

        #pragma unroll
        for (int i = 0; i < 8; i++) sc2[i] = __float2half2_rn(0.f);

        for (int h = 0; h < HH; h += 2) {
            const float ab0 = sAb[h], ab1 = sAb[h + 1];
            float acc0[16], acc1[16];
            #pragma unroll
            for (int i = 0; i < 16; i++) { acc0[i] = ab0; acc1[i] = ab1; }  // bias folded in

            const uint32_t aA0 = aBase + (uint32_t)(h * 9216);
            const uint32_t aA1 = aA0 + 9216;
            #pragma unroll
            for (int ks = 0; ks < 4; ks++) {
                const uint32_t d0b = (uint32_t)(ks * 32);
                uint32_t bb[8];
                ldsm_x4(bb, bBase + d0b);                       // tokens n0..n0+15
                if (wide) ldsm_x4(bb + 4, bBase + 2304 + d0b);  // tokens n0+16..n0+31
                else      ldsm_x2(bb + 4, b2Base + d0b);        // tokens n0+16..n0+23
                uint32_t af0[4], af1[4];
                ldsm_x4(af0, aA0 + d0b);
                ldsm_x4(af1, aA1 + d0b);
                mma_f16(acc0 + 0, af0, bb[0], bb[1]);
                mma_f16(acc0 + 4, af0, bb[2], bb[3]);
                mma_f16(acc0 + 8, af0, bb[4], bb[5]);
                mma_f16(acc1 + 0, af1, bb[0], bb[1]);
                mma_f16(acc1 + 4, af1, bb[2], bb[3]);
                mma_f16(acc1 + 8, af1, bb[4], bb[5]);
                if (wide) {
                    mma_f16(acc0 + 12, af0, bb[6], bb[7]);
                    mma_f16(acc1 + 12, af1, bb[6], bb[7]);
                }
            }

            // epilogue: sc2 += ao * tanh(acc)  — 2 elems per MUFU op
            const __half2 ao0h = __float2half2_rn(sAo[h]);
            const __half2 ao1h = __float2half2_rn(sAo[h + 1]);
            const int npair = wide ? 8 : 6;
            #pragma unroll
            for (int i = 0; i < 8; i++) {
                if (i < npair) {
                    uint32_t t0p = tanh2(pack_h2(acc0[2 * i], acc0[2 * i + 1]));
                    sc2[i] = __hfma2(ao0h, *(__half2*)&t0p, sc2[i]);
                    uint32_t t1p = tanh2(pack_h2(acc1[2 * i], acc1[2 * i + 1]));
                    sc2[i] = __hfma2(ao1h, *(__half2*)&t1p, sc2[i]);
                }
            }
        }
    }

    // ---------------- Phase D: softmax + decay -> fp16 P ----------------
    {
        const int nOct = wide ? 4 : 3;
        float ev[16];
        float se = 0.f, so = 0.f;
        #pragma unroll
        for (int o = 0; o < 4; o++) {
            if (o < nOct) {
                int c = n0 + 8 * o + q2;
                float2 v = *(float2*)&sVal[c];
                float s0 = __low2float(sc2[2 * o]);
                float s1 = __high2float(sc2[2 * o]);
                float s2 = __low2float(sc2[2 * o + 1]);
                float s3 = __high2float(sc2[2 * o + 1]);
                float e0 = v.x * __expf(s0);
                float e1 = v.y * __expf(s1);
                float e2 = v.x * __expf(s2);
                float e3 = v.y * __expf(s3);
                ev[4 * o + 0] = e0; ev[4 * o + 1] = e1;
                ev[4 * o + 2] = e2; ev[4 * o + 3] = e3;
                se += e0 + e1;
                so += e2 + e3;
            }
        }
        se += __shfl_xor_sync(0xffffffffu, se, 1);
        se += __shfl_xor_sync(0xffffffffu, se, 2);
        so += __shfl_xor_sync(0xffffffffu, so, 1);
        so += __shfl_xor_sync(0xffffffffu, so, 2);
        if ((lane & 3) == 0) {
            sPart[(t0 + g) * 8 + ng]     = se;
            sPart[(t0 + g + 8) * 8 + ng] = so;
        }
        __syncthreads();   // phase C smem reads done + partials visible

        float4 pe0 = ((float4*)&sPart[(t0 + g) * 8])[0];
        float4 pe1 = ((float4*)&sPart[(t0 + g) * 8])[1];
        float4 po0 = ((float4*)&sPart[(t0 + g + 8) * 8])[0];
        float4 po1 = ((float4*)&sPart[(t0 + g + 8) * 8])[1];
        const float invE = __fdividef(1.f, pe0.x + pe0.y + pe0.z + pe0.w + pe1.x + pe1.y + pe1.z + pe1.w);
        const float invO = __fdividef(1.f, po0.x + po0.y + po0.z + po0.w + po1.x + po1.y + po1.z + po1.w);

        char* rowE = smc + P_B + (t0 + g) * PSTRIDE;
        char* rowO = smc + P_B + (t0 + g + 8) * PSTRIDE;
        #pragma unroll
        for (int o = 0; o < 4; o++) {
            if (o < nOct) {
                int c = n0 + 8 * o + q2;
                float2 d = *(float2*)&sDec[c];
                *(__half2*)(rowE + c * 2) =
                    __floats2half2_rn(ev[4 * o + 0] * invE * d.x, ev[4 * o + 1] * invE * d.y);
                *(__half2*)(rowO + c * 2) =
                    __floats2half2_rn(ev[4 * o + 2] * invO * d.x, ev[4 * o + 3] * invO * d.y);
            }
        }
    }
    __syncthreads();

    // ---------------- Phase E: context = P @ seq via MMA (28 tiles: 4t x 7dg) ----------------
    {
        const uint32_t rowSel = (uint32_t)((lane & 7) + ((lane >> 3) & 1) * 8);
        const int rr = lane >> 2, cc = (lane & 3) * 2;
        float* gout = out + (size_t)b * TQ * DD;

        const int tg2 = warp / 7;          // 0..3
        const int dg  = warp % 7;          // 0..6
        const int t0e = tg2 * 16;
        const uint32_t pBase = sbase + P_B + (uint32_t)((t0e + rowSel) * PSTRIDE)
                             + (uint32_t)((lane >> 4) * 16);
        if (dg < 6) {
            const int d0 = dg * 8;         // 8-wide tile
            const uint32_t kBase = sbase + SEQK_B + rowSel * ASTRIDE + (uint32_t)(d0 * 2);
            float accA[4] = {0.f, 0.f, 0.f, 0.f};
            #pragma unroll
            for (int kc = 0; kc < 13; kc++) {
                uint32_t a[4], bb2[2];
                ldsm_x4(a, pBase + (uint32_t)(kc * 32));
                ldsm_x2t(bb2, kBase + (uint32_t)(kc * 16) * ASTRIDE);
                mma_f16(accA, a, bb2[0], bb2[1]);
            }
            *(float2*)(gout + (t0e + rr) * 64 + d0 + cc)     = make_float2(accA[0], accA[1]);
            *(float2*)(gout + (t0e + rr + 8) * 64 + d0 + cc) = make_float2(accA[2], accA[3]);
        } else {
            const int d0 = 48;             // 16-wide tile (cols 48..63)
            const uint32_t kBase = sbase + SEQK_B + rowSel * ASTRIDE
                                 + (uint32_t)((d0 + ((lane >> 4) * 8)) * 2);
            float accA[4] = {0.f, 0.f, 0.f, 0.f};
            float accB[4] = {0.f, 0.f, 0.f, 0.f};
            #pragma unroll
            for (int kc = 0; kc < 13; kc++) {
                uint32_t a[4], bb[4];
                ldsm_x4(a, pBase + (uint32_t)(kc * 32));
                ldsm_x4t(bb, kBase + (uint32_t)(kc * 16) * ASTRIDE);
                mma_f16(accA, a, bb[0], bb[1]);
                mma_f16(accB, a, bb[2], bb[3]);
            }
            *(float2*)(gout + (t0e + rr) * 64 + d0 + cc)         = make_float2(accA[0], accA[1]);
            *(float2*)(gout + (t0e + rr + 8) * 64 + d0 + cc)     = make_float2(accA[2], accA[3]);
            *(float2*)(gout + (t0e + rr) * 64 + d0 + 8 + cc)     = make_float2(accB[0], accB[1]);
            *(float2*)(gout + (t0e + rr + 8) * 64 + d0 + 8 + cc) = make_float2(accB[2], accB[3]);
        }
    }
}

extern "C" void kernel_launch(void* const* d_in, const int* in_sizes, int n_in,
                              void* d_out, int out_size)
{
    const float* seq    = (const float*)d_in[0];
    const float* dtn    = (const float*)d_in[1];
    const float* target = (const float*)d_in[2];
    const int*   vmask  = (const int*)  d_in[3];
    const float* fr     = (const float*)d_in[4];
    const float* fi     = (const float*)d_in[5];
    const float* Aw     = (const float*)d_in[6];
    const float* Ab     = (const float*)d_in[7];
    const float* Aout   = (const float*)d_in[8];
    float* out = (float*)d_out;

    cudaFuncSetAttribute(fta_kernel, cudaFuncAttributeMaxDynamicSharedMemorySize, SMEM_TOTAL_B);
    fta_kernel<<<BB, NTHREADS, SMEM_TOTAL_B>>>(seq, dtn, target, vmask, fr, fi, Aw, Ab, Aout, out);
}